// round 1
// baseline (speedup 1.0000x reference)
#include <cuda_runtime.h>
#include <cstdint>
#include <cstdio>

// Problem constants (fixed shapes for this problem instance)
#define Bn   16
#define ND   8192
#define NE   16384
#define NEDGE 65536
#define H    128
#define HPAD 132   // padded W row stride in smem (132 mod 32 = 4 -> conflict-free float4)

// ---------------- scratch (static __device__: allocation-free) ----------------
__device__ float g_Y[(size_t)Bn * ND * H];     // 64 MB : hD @ W_d2e^T
__device__ float g_Z[(size_t)Bn * NE * H];     // 128 MB: hE_new @ W_e2d^T
__device__ float g_aggE[(size_t)Bn * NE * H];  // 128 MB
__device__ float g_aggD[(size_t)Bn * ND * H];  // 64 MB

__device__ int g_cntE[NE];
__device__ int g_offE[NE + 1];
__device__ int g_curE[NE];
__device__ int g_lstE[NEDGE];

__device__ int g_cntD[ND];
__device__ int g_offD[ND + 1];
__device__ int g_curD[ND];
__device__ int g_lstD[NEDGE];

// ---------------- CSR construction ----------------
__global__ void k_count(const int* __restrict__ e_d2e, const int* __restrict__ e_e2d) {
    int e = blockIdx.x * blockDim.x + threadIdx.x;
    if (e >= NEDGE) return;
    atomicAdd(&g_cntE[e_d2e[NEDGE + e]], 1);   // row1 = dst
    atomicAdd(&g_cntD[e_e2d[NEDGE + e]], 1);
}

// single-block exclusive scan (n is a multiple of 1024)
__global__ void k_scan(const int* __restrict__ cnt, int* __restrict__ off,
                       int* __restrict__ cur, int n) {
    __shared__ int sm[1024];
    __shared__ int s_run;
    int tid = threadIdx.x;
    if (tid == 0) s_run = 0;
    __syncthreads();
    for (int base = 0; base < n; base += 1024) {
        int v = (base + tid < n) ? cnt[base + tid] : 0;
        sm[tid] = v;
        __syncthreads();
        for (int d = 1; d < 1024; d <<= 1) {
            int t = (tid >= d) ? sm[tid - d] : 0;
            __syncthreads();
            sm[tid] += t;
            __syncthreads();
        }
        int incl = sm[tid];
        int run = s_run;
        if (base + tid < n) {
            off[base + tid] = run + incl - v;
            cur[base + tid] = run + incl - v;
        }
        __syncthreads();
        if (tid == 1023) s_run = run + incl;
        __syncthreads();
    }
    if (tid == 0) off[n] = s_run;
}

__global__ void k_fill(const int* __restrict__ e_d2e, const int* __restrict__ e_e2d) {
    int e = blockIdx.x * blockDim.x + threadIdx.x;
    if (e >= NEDGE) return;
    {
        int d = e_d2e[NEDGE + e];
        int p = atomicAdd(&g_curE[d], 1);
        g_lstE[p] = e_d2e[e];                   // row0 = src
    }
    {
        int d = e_e2d[NEDGE + e];
        int p = atomicAdd(&g_curD[d], 1);
        g_lstD[p] = e_e2d[e];
    }
}

// ---------------- aggregation: warp per (node, batch) ----------------
// agg[b,node,:] = scale * sum_{src in list(node)} SRC[b,src,:]
// scale = sigmoid(ew[node]) / max(deg,1)   (ew == nullptr for phase 2)
__global__ void k_agg(const float* __restrict__ SRC, const int* __restrict__ off,
                      const int* __restrict__ lst, const float* __restrict__ ew,
                      float* __restrict__ agg, int nNodes, long srcStride) {
    int gw = (blockIdx.x * blockDim.x + threadIdx.x) >> 5;
    if (gw >= nNodes * Bn) return;
    int node = gw % nNodes;
    int b    = gw / nNodes;
    int lane = threadIdx.x & 31;

    int s = off[node], e = off[node + 1];
    float4 a = make_float4(0.f, 0.f, 0.f, 0.f);
    const float* base = SRC + (size_t)b * srcStride;
    for (int j = s; j < e; ++j) {
        int src = lst[j];
        float4 v = reinterpret_cast<const float4*>(base + (size_t)src * H)[lane];
        a.x += v.x; a.y += v.y; a.z += v.z; a.w += v.w;
    }
    float sc = 1.0f / fmaxf((float)(e - s), 1.0f);
    if (ew) sc *= 1.0f / (1.0f + __expf(-ew[node]));
    a.x *= sc; a.y *= sc; a.z *= sc; a.w *= sc;
    reinterpret_cast<float4*>(agg + ((size_t)b * nNodes + node) * H)[lane] = a;
}

// ---------------- GEMM (+ optional fused epilogue) ----------------
// 128 threads; each thread owns one output column; 32 rows per block.
// MODE 0: out = X @ W^T
// MODE 1: out = LayerNorm(X + relu(X@W^T + agg + bias)) * gamma + beta
template <int MODE>
__global__ void __launch_bounds__(128)
k_gemm(const float* __restrict__ X, const float* __restrict__ W,
       const float* __restrict__ agg, const float* __restrict__ bias,
       const float* __restrict__ gamma, const float* __restrict__ beta,
       float* __restrict__ out) {
    extern __shared__ float smx[];
    float* Ws = smx;                 // 128 * HPAD
    float* xs = smx + 128 * HPAD;    // 32 * 128
    int tid = threadIdx.x;

    for (int i = tid; i < H * H; i += 128)
        Ws[(i >> 7) * HPAD + (i & 127)] = W[i];

    size_t row0 = (size_t)blockIdx.x * 32;
    const float* Xb = X + row0 * H;
    for (int i = tid; i < 32 * H; i += 128)
        xs[i] = Xb[i];
    __syncthreads();

    float acc[32];
#pragma unroll
    for (int r = 0; r < 32; ++r) acc[r] = 0.f;

    const float* wrow = Ws + tid * HPAD;
    for (int h = 0; h < H; h += 4) {
        float4 w4 = *reinterpret_cast<const float4*>(wrow + h);
#pragma unroll
        for (int r = 0; r < 32; ++r) {
            float4 x4 = *reinterpret_cast<const float4*>(xs + r * H + h);
            acc[r] = fmaf(w4.x, x4.x,
                     fmaf(w4.y, x4.y,
                     fmaf(w4.z, x4.z,
                     fmaf(w4.w, x4.w, acc[r]))));
        }
    }

    if (MODE == 0) {
#pragma unroll
        for (int r = 0; r < 32; ++r)
            out[(row0 + r) * H + tid] = acc[r];
    } else {
        float bo = bias[tid], go = gamma[tid], be = beta[tid];
#pragma unroll
        for (int r = 0; r < 32; ++r) {
            float a = agg[(row0 + r) * H + tid];
            float pre = acc[r] + a + bo;
            pre = pre > 0.f ? pre : 0.f;
            acc[r] = xs[r * H + tid] + pre;   // residual; acc now holds t
        }
        // LayerNorm over the 128 columns of each row
        __shared__ float ps[32][4], qs[32][4], s_m[32], s_r[32];
        int lane = tid & 31, wid = tid >> 5;
#pragma unroll
        for (int r = 0; r < 32; ++r) {
            float s = acc[r], q = acc[r] * acc[r];
#pragma unroll
            for (int o = 16; o; o >>= 1) {
                s += __shfl_down_sync(0xffffffffu, s, o);
                q += __shfl_down_sync(0xffffffffu, q, o);
            }
            if (lane == 0) { ps[r][wid] = s; qs[r][wid] = q; }
        }
        __syncthreads();
        if (tid < 32) {
            float s = ps[tid][0] + ps[tid][1] + ps[tid][2] + ps[tid][3];
            float q = qs[tid][0] + qs[tid][1] + qs[tid][2] + qs[tid][3];
            float m = s * (1.0f / 128.0f);
            float v = q * (1.0f / 128.0f) - m * m;
            s_m[tid] = m;
            s_r[tid] = rsqrtf(v + 1e-5f);
        }
        __syncthreads();
#pragma unroll
        for (int r = 0; r < 32; ++r)
            out[(row0 + r) * H + tid] = (acc[r] - s_m[r]) * s_r[r] * go + be;
    }
}

// ---------------- launch ----------------
extern "C" void kernel_launch(void* const* d_in, const int* in_sizes, int n_in,
                              void* d_out, int out_size) {
    const float* hD   = (const float*)d_in[0];
    const float* hE   = (const float*)d_in[1];
    const int*   e_d2e = (const int*)d_in[2];
    const int*   e_e2d = (const int*)d_in[3];
    const float* ew   = (const float*)d_in[4];
    const float* W_d2e   = (const float*)d_in[5];
    const float* W_e_self= (const float*)d_in[6];
    const float* b_e  = (const float*)d_in[7];
    const float* g_e  = (const float*)d_in[8];
    const float* be_e = (const float*)d_in[9];
    const float* W_e2d   = (const float*)d_in[10];
    const float* W_d_self= (const float*)d_in[11];
    const float* b_d  = (const float*)d_in[12];
    const float* g_d  = (const float*)d_in[13];
    const float* be_d = (const float*)d_in[14];

    float* out_hD = (float*)d_out;                              // [B, ND, H]
    float* out_hE = (float*)d_out + (size_t)Bn * ND * H;        // [B, NE, H]

    // resolve scratch symbols (host API, no allocation)
    float *pY, *pZ, *pAggE, *pAggD;
    int *pCntE, *pOffE, *pCurE, *pLstE, *pCntD, *pOffD, *pCurD, *pLstD;
    cudaGetSymbolAddress((void**)&pY, g_Y);
    cudaGetSymbolAddress((void**)&pZ, g_Z);
    cudaGetSymbolAddress((void**)&pAggE, g_aggE);
    cudaGetSymbolAddress((void**)&pAggD, g_aggD);
    cudaGetSymbolAddress((void**)&pCntE, g_cntE);
    cudaGetSymbolAddress((void**)&pOffE, g_offE);
    cudaGetSymbolAddress((void**)&pCurE, g_curE);
    cudaGetSymbolAddress((void**)&pLstE, g_lstE);
    cudaGetSymbolAddress((void**)&pCntD, g_cntD);
    cudaGetSymbolAddress((void**)&pOffD, g_offD);
    cudaGetSymbolAddress((void**)&pCurD, g_curD);
    cudaGetSymbolAddress((void**)&pLstD, g_lstD);

    const int smem = (128 * HPAD + 32 * H) * (int)sizeof(float);  // ~84 KB
    cudaFuncSetAttribute(k_gemm<0>, cudaFuncAttributeMaxDynamicSharedMemorySize, smem);
    cudaFuncSetAttribute(k_gemm<1>, cudaFuncAttributeMaxDynamicSharedMemorySize, smem);

    // ---- CSR build (both phases) ----
    cudaMemsetAsync(pCntE, 0, NE * sizeof(int));
    cudaMemsetAsync(pCntD, 0, ND * sizeof(int));
    k_count<<<(NEDGE + 255) / 256, 256>>>(e_d2e, e_e2d);
    k_scan<<<1, 1024>>>(pCntE, pOffE, pCurE, NE);
    k_scan<<<1, 1024>>>(pCntD, pOffD, pCurD, ND);
    k_fill<<<(NEDGE + 255) / 256, 256>>>(e_d2e, e_e2d);

    // ---- Phase 1: D -> E ----
    k_gemm<0><<<(Bn * ND) / 32, 128, smem>>>(hD, W_d2e, nullptr, nullptr, nullptr, nullptr, pY);
    {
        int warps = NE * Bn;
        k_agg<<<(warps * 32) / 256, 256>>>(pY, pOffE, pLstE, ew, pAggE, NE, (long)ND * H);
    }
    k_gemm<1><<<(Bn * NE) / 32, 128, smem>>>(hE, W_e_self, pAggE, b_e, g_e, be_e, out_hE);

    // ---- Phase 2: E -> D ----
    k_gemm<0><<<(Bn * NE) / 32, 128, smem>>>(out_hE, W_e2d, nullptr, nullptr, nullptr, nullptr, pZ);
    {
        int warps = ND * Bn;
        k_agg<<<(warps * 32) / 256, 256>>>(pZ, pOffD, pLstD, nullptr, pAggD, ND, (long)NE * H);
    }
    k_gemm<1><<<(Bn * ND) / 32, 128, smem>>>(hD, W_d_self, pAggD, b_d, g_d, be_d, out_hD);
}

// round 2
// speedup vs baseline: 2.5899x; 2.5899x over previous
#include <cuda_runtime.h>
#include <cstdint>

// Problem constants
#define Bn   16
#define ND   8192
#define NE   16384
#define NEDGE 65536
#define H    128

typedef unsigned long long u64;

// ---------------- scratch (static __device__: allocation-free) ----------------
__device__ float g_Y[(size_t)Bn * ND * H];     // hD @ W_d2e^T
__device__ float g_Z[(size_t)Bn * NE * H];     // hE_new @ W_e2d^T
__device__ float g_aggE[(size_t)Bn * NE * H];
__device__ float g_aggD[(size_t)Bn * ND * H];
__device__ float g_Wt[4][H * H];               // transposed weights [k][c]

__device__ int g_cntE[NE];
__device__ int g_offE[NE + 1];
__device__ int g_curE[NE];
__device__ int g_lstE[NEDGE];

__device__ int g_cntD[ND];
__device__ int g_offD[ND + 1];
__device__ int g_curD[ND];
__device__ int g_lstD[NEDGE];

// ---------------- weight transpose: Wt[k][c] = W[c][k] ----------------
__global__ void k_wt(const float* __restrict__ W, float* __restrict__ Wt) {
    int idx = blockIdx.x * blockDim.x + threadIdx.x;   // 0..16383
    int k = idx >> 7, c = idx & 127;
    Wt[idx] = W[c * H + k];
}

// ---------------- CSR construction ----------------
__global__ void k_count(const int* __restrict__ e_d2e, const int* __restrict__ e_e2d) {
    int e = blockIdx.x * blockDim.x + threadIdx.x;
    if (e >= NEDGE) return;
    atomicAdd(&g_cntE[e_d2e[NEDGE + e]], 1);
    atomicAdd(&g_cntD[e_e2d[NEDGE + e]], 1);
}

__global__ void k_scan(const int* __restrict__ cnt, int* __restrict__ off,
                       int* __restrict__ cur, int n) {
    __shared__ int sm[1024];
    __shared__ int s_run;
    int tid = threadIdx.x;
    if (tid == 0) s_run = 0;
    __syncthreads();
    for (int base = 0; base < n; base += 1024) {
        int v = (base + tid < n) ? cnt[base + tid] : 0;
        sm[tid] = v;
        __syncthreads();
        for (int d = 1; d < 1024; d <<= 1) {
            int t = (tid >= d) ? sm[tid - d] : 0;
            __syncthreads();
            sm[tid] += t;
            __syncthreads();
        }
        int incl = sm[tid];
        int run = s_run;
        if (base + tid < n) {
            off[base + tid] = run + incl - v;
            cur[base + tid] = run + incl - v;
        }
        __syncthreads();
        if (tid == 1023) s_run = run + incl;
        __syncthreads();
    }
    if (tid == 0) off[n] = s_run;
}

__global__ void k_fill(const int* __restrict__ e_d2e, const int* __restrict__ e_e2d) {
    int e = blockIdx.x * blockDim.x + threadIdx.x;
    if (e >= NEDGE) return;
    {
        int d = e_d2e[NEDGE + e];
        int p = atomicAdd(&g_curE[d], 1);
        g_lstE[p] = e_d2e[e];
    }
    {
        int d = e_e2d[NEDGE + e];
        int p = atomicAdd(&g_curD[d], 1);
        g_lstD[p] = e_e2d[e];
    }
}

// ---------------- aggregation: warp per (node, batch) ----------------
__global__ void k_agg(const float* __restrict__ SRC, const int* __restrict__ off,
                      const int* __restrict__ lst, const float* __restrict__ ew,
                      float* __restrict__ agg, int nNodes, long srcStride) {
    int gw = (blockIdx.x * blockDim.x + threadIdx.x) >> 5;
    if (gw >= nNodes * Bn) return;
    int node = gw % nNodes;
    int b    = gw / nNodes;
    int lane = threadIdx.x & 31;

    int s = off[node], e = off[node + 1];
    float4 a = make_float4(0.f, 0.f, 0.f, 0.f);
    const float* base = SRC + (size_t)b * srcStride;
    for (int j = s; j < e; ++j) {
        int src = lst[j];
        float4 v = reinterpret_cast<const float4*>(base + (size_t)src * H)[lane];
        a.x += v.x; a.y += v.y; a.z += v.z; a.w += v.w;
    }
    float sc = 1.0f / fmaxf((float)(e - s), 1.0f);
    if (ew) sc *= 1.0f / (1.0f + __expf(-ew[node]));
    a.x *= sc; a.y *= sc; a.z *= sc; a.w *= sc;
    reinterpret_cast<float4*>(agg + ((size_t)b * nNodes + node) * H)[lane] = a;
}

// ---------------- register-tiled GEMM (+ fused epilogue) ----------------
// 256 threads; block tile = 128 rows x 128 cols; thread tile = 8 rows x 8 cols
// (4 contiguous col-pairs, strided by 32). All math in packed fma.rn.f32x2.
// MODE 0: out = X @ Wt            (Wt pre-transposed: Wt[k][c])
// MODE 1: out = LN(X + relu(X@Wt + agg + bias)) * gamma + beta
template <int MODE>
__global__ void __launch_bounds__(256, 1)
k_gemm(const float* __restrict__ X, const float* __restrict__ Wt,
       const float* __restrict__ agg, const float* __restrict__ bias,
       const float* __restrict__ gamma, const float* __restrict__ beta,
       float* __restrict__ out) {
    extern __shared__ float smx[];
    float* Xs = smx;              // [128][128] row-major (r, k)
    float* Ws = smx + 128 * 128;  // [128][128] (k, c)
    const int t = threadIdx.x;
    const size_t row0 = (size_t)blockIdx.x * 128;

    {
        const float4* Xg = reinterpret_cast<const float4*>(X + row0 * H);
        const float4* Wg = reinterpret_cast<const float4*>(Wt);
        float4* Xs4 = reinterpret_cast<float4*>(Xs);
        float4* Ws4 = reinterpret_cast<float4*>(Ws);
#pragma unroll
        for (int i = 0; i < 16; i++) {
            Xs4[t + 256 * i] = Xg[t + 256 * i];
            Ws4[t + 256 * i] = Wg[t + 256 * i];
        }
    }
    __syncthreads();

    const int tc = t & 15, tr = t >> 4;
    // acc[i][j]: rows tr*8+i, cols (2*tc+32*j, 2*tc+32*j+1) packed f32x2
    u64 acc[8][4];
#pragma unroll
    for (int i = 0; i < 8; i++)
#pragma unroll
        for (int j = 0; j < 4; j++) acc[i][j] = 0ull;

    const float* xbase = Xs + tr * 8 * 128;
    const float* wbase = Ws + 2 * tc;

#pragma unroll 4
    for (int k = 0; k < 128; k++) {
        u64 wv[4];
#pragma unroll
        for (int j = 0; j < 4; j++)
            wv[j] = *reinterpret_cast<const u64*>(wbase + k * 128 + 32 * j);
#pragma unroll
        for (int i = 0; i < 8; i++) {
            float xv = xbase[i * 128 + k];
            u64 xd;
            asm("mov.b64 %0, {%1, %1};" : "=l"(xd) : "f"(xv));
#pragma unroll
            for (int j = 0; j < 4; j++)
                asm("fma.rn.f32x2 %0, %1, %2, %0;"
                    : "+l"(acc[i][j]) : "l"(wv[j]), "l"(xd));
        }
    }

    if (MODE == 0) {
#pragma unroll
        for (int i = 0; i < 8; i++) {
            float* orow = out + (row0 + tr * 8 + i) * H + 2 * tc;
#pragma unroll
            for (int j = 0; j < 4; j++)
                *reinterpret_cast<u64*>(orow + 32 * j) = acc[i][j];
        }
    } else {
        float2 b2[4], g2[4], be2[4];
#pragma unroll
        for (int j = 0; j < 4; j++) {
            b2[j]  = *reinterpret_cast<const float2*>(bias  + 2 * tc + 32 * j);
            g2[j]  = *reinterpret_cast<const float2*>(gamma + 2 * tc + 32 * j);
            be2[j] = *reinterpret_cast<const float2*>(beta  + 2 * tc + 32 * j);
        }
#pragma unroll
        for (int i = 0; i < 8; i++) {
            const size_t r = row0 + tr * 8 + i;
            float tv[8];
            float s = 0.f, q = 0.f;
#pragma unroll
            for (int j = 0; j < 4; j++) {
                float2 a2 = *reinterpret_cast<const float2*>(agg + r * H + 2 * tc + 32 * j);
                float plo, phi;
                asm("mov.b64 {%0, %1}, %2;" : "=f"(plo), "=f"(phi) : "l"(acc[i][j]));
                float2 x2 = *reinterpret_cast<const float2*>(Xs + (tr * 8 + i) * 128 + 2 * tc + 32 * j);
                float t0 = plo + a2.x + b2[j].x; t0 = fmaxf(t0, 0.f); t0 += x2.x;
                float t1 = phi + a2.y + b2[j].y; t1 = fmaxf(t1, 0.f); t1 += x2.y;
                tv[2 * j]     = t0;
                tv[2 * j + 1] = t1;
                s += t0 + t1;
                q += t0 * t0 + t1 * t1;
            }
#pragma unroll
            for (int o = 8; o; o >>= 1) {
                s += __shfl_xor_sync(0xffffffffu, s, o, 16);
                q += __shfl_xor_sync(0xffffffffu, q, o, 16);
            }
            float m = s * (1.0f / 128.0f);
            float rstd = rsqrtf(q * (1.0f / 128.0f) - m * m + 1e-5f);
            float* orow = out + r * H + 2 * tc;
#pragma unroll
            for (int j = 0; j < 4; j++) {
                float2 o2;
                o2.x = (tv[2 * j]     - m) * rstd * g2[j].x + be2[j].x;
                o2.y = (tv[2 * j + 1] - m) * rstd * g2[j].y + be2[j].y;
                *reinterpret_cast<float2*>(orow + 32 * j) = o2;
            }
        }
    }
}

// ---------------- launch ----------------
extern "C" void kernel_launch(void* const* d_in, const int* in_sizes, int n_in,
                              void* d_out, int out_size) {
    const float* hD    = (const float*)d_in[0];
    const float* hE    = (const float*)d_in[1];
    const int*   e_d2e = (const int*)d_in[2];
    const int*   e_e2d = (const int*)d_in[3];
    const float* ew    = (const float*)d_in[4];
    const float* W_d2e    = (const float*)d_in[5];
    const float* W_e_self = (const float*)d_in[6];
    const float* b_e   = (const float*)d_in[7];
    const float* g_e   = (const float*)d_in[8];
    const float* be_e  = (const float*)d_in[9];
    const float* W_e2d    = (const float*)d_in[10];
    const float* W_d_self = (const float*)d_in[11];
    const float* b_d   = (const float*)d_in[12];
    const float* g_d   = (const float*)d_in[13];
    const float* be_d  = (const float*)d_in[14];

    float* out_hD = (float*)d_out;
    float* out_hE = (float*)d_out + (size_t)Bn * ND * H;

    float *pY, *pZ, *pAggE, *pAggD, *pWt;
    int *pCntE, *pOffE, *pCurE, *pLstE, *pCntD, *pOffD, *pCurD, *pLstD;
    cudaGetSymbolAddress((void**)&pY, g_Y);
    cudaGetSymbolAddress((void**)&pZ, g_Z);
    cudaGetSymbolAddress((void**)&pAggE, g_aggE);
    cudaGetSymbolAddress((void**)&pAggD, g_aggD);
    cudaGetSymbolAddress((void**)&pWt, g_Wt);
    cudaGetSymbolAddress((void**)&pCntE, g_cntE);
    cudaGetSymbolAddress((void**)&pOffE, g_offE);
    cudaGetSymbolAddress((void**)&pCurE, g_curE);
    cudaGetSymbolAddress((void**)&pLstE, g_lstE);
    cudaGetSymbolAddress((void**)&pCntD, g_cntD);
    cudaGetSymbolAddress((void**)&pOffD, g_offD);
    cudaGetSymbolAddress((void**)&pCurD, g_curD);
    cudaGetSymbolAddress((void**)&pLstD, g_lstD);

    float* Wt_d2e    = pWt + 0 * H * H;
    float* Wt_e_self = pWt + 1 * H * H;
    float* Wt_e2d    = pWt + 2 * H * H;
    float* Wt_d_self = pWt + 3 * H * H;

    const int smem = 2 * 128 * 128 * (int)sizeof(float);  // 128 KB
    cudaFuncSetAttribute(k_gemm<0>, cudaFuncAttributeMaxDynamicSharedMemorySize, smem);
    cudaFuncSetAttribute(k_gemm<1>, cudaFuncAttributeMaxDynamicSharedMemorySize, smem);

    // ---- weight transposes + CSR build ----
    k_wt<<<64, 256>>>(W_d2e, Wt_d2e);
    k_wt<<<64, 256>>>(W_e_self, Wt_e_self);
    k_wt<<<64, 256>>>(W_e2d, Wt_e2d);
    k_wt<<<64, 256>>>(W_d_self, Wt_d_self);

    cudaMemsetAsync(pCntE, 0, NE * sizeof(int));
    cudaMemsetAsync(pCntD, 0, ND * sizeof(int));
    k_count<<<(NEDGE + 255) / 256, 256>>>(e_d2e, e_e2d);
    k_scan<<<1, 1024>>>(pCntE, pOffE, pCurE, NE);
    k_scan<<<1, 1024>>>(pCntD, pOffD, pCurD, ND);
    k_fill<<<(NEDGE + 255) / 256, 256>>>(e_d2e, e_e2d);

    // ---- Phase 1: D -> E ----
    k_gemm<0><<<(Bn * ND) / 128, 256, smem>>>(hD, Wt_d2e, nullptr, nullptr, nullptr, nullptr, pY);
    k_agg<<<(NE * Bn * 32) / 256, 256>>>(pY, pOffE, pLstE, ew, pAggE, NE, (long)ND * H);
    k_gemm<1><<<(Bn * NE) / 128, 256, smem>>>(hE, Wt_e_self, pAggE, b_e, g_e, be_e, out_hE);

    // ---- Phase 2: E -> D ----
    k_gemm<0><<<(Bn * NE) / 128, 256, smem>>>(out_hE, Wt_e2d, nullptr, nullptr, nullptr, nullptr, pZ);
    k_agg<<<(ND * Bn * 32) / 256, 256>>>(pZ, pOffD, pLstD, nullptr, pAggD, ND, (long)NE * H);
    k_gemm<1><<<(Bn * ND) / 128, 256, smem>>>(hD, Wt_d_self, pAggD, b_d, g_d, be_d, out_hD);
}

// round 3
// speedup vs baseline: 2.9471x; 1.1379x over previous
#include <cuda_runtime.h>
#include <cstdint>

#define Bn   16
#define ND   8192
#define NE   16384
#define NEDGE 65536
#define H    128

typedef unsigned long long u64;

// ---------------- scratch (static __device__: allocation-free) ----------------
__device__ float g_Y[(size_t)Bn * ND * H];       // hD @ W_d2e^T        (64 MB)
__device__ float g_aggPre[(size_t)Bn * ND * H];  // mean gather hE_new  (64 MB)
__device__ float g_Wt[4][H * H];                 // transposed weights [k][c]

__device__ int g_cntE[NE];
__device__ int g_offE[NE + 1];
__device__ int g_curE[NE];
__device__ int g_lstE[NEDGE];

__device__ int g_cntD[ND];
__device__ int g_offD[ND + 1];
__device__ int g_curD[ND];
__device__ int g_lstD[NEDGE];

// ---------------- weight transpose: Wt[k][c] = W[c][k] ----------------
__global__ void k_wt(const float* __restrict__ W, float* __restrict__ Wt) {
    int idx = blockIdx.x * blockDim.x + threadIdx.x;
    int k = idx >> 7, c = idx & 127;
    Wt[idx] = W[c * H + k];
}

// ---------------- CSR construction ----------------
__global__ void k_count(const int* __restrict__ e_d2e, const int* __restrict__ e_e2d) {
    int e = blockIdx.x * blockDim.x + threadIdx.x;
    if (e >= NEDGE) return;
    atomicAdd(&g_cntE[e_d2e[NEDGE + e]], 1);
    atomicAdd(&g_cntD[e_e2d[NEDGE + e]], 1);
}

__global__ void k_scan(const int* __restrict__ cnt, int* __restrict__ off,
                       int* __restrict__ cur, int n) {
    __shared__ int sm[1024];
    __shared__ int s_run;
    int tid = threadIdx.x;
    if (tid == 0) s_run = 0;
    __syncthreads();
    for (int base = 0; base < n; base += 1024) {
        int v = (base + tid < n) ? cnt[base + tid] : 0;
        sm[tid] = v;
        __syncthreads();
        for (int d = 1; d < 1024; d <<= 1) {
            int t = (tid >= d) ? sm[tid - d] : 0;
            __syncthreads();
            sm[tid] += t;
            __syncthreads();
        }
        int incl = sm[tid];
        int run = s_run;
        if (base + tid < n) {
            off[base + tid] = run + incl - v;
            cur[base + tid] = run + incl - v;
        }
        __syncthreads();
        if (tid == 1023) s_run = run + incl;
        __syncthreads();
    }
    if (tid == 0) off[n] = s_run;
}

__global__ void k_fill(const int* __restrict__ e_d2e, const int* __restrict__ e_e2d) {
    int e = blockIdx.x * blockDim.x + threadIdx.x;
    if (e >= NEDGE) return;
    {
        int d = e_d2e[NEDGE + e];
        int p = atomicAdd(&g_curE[d], 1);
        g_lstE[p] = e_d2e[e];
    }
    {
        int d = e_e2d[NEDGE + e];
        int p = atomicAdd(&g_curD[d], 1);
        g_lstD[p] = e_e2d[e];
    }
}

// ---------------- mean-gather: warp per (node, batch) ----------------
// aggPre[b,node,:] = (1/max(deg,1)) * sum_{src in list(node)} SRC[b,src,:]
__global__ void k_agg(const float* __restrict__ SRC, const int* __restrict__ off,
                      const int* __restrict__ lst, float* __restrict__ agg,
                      int nNodes, long srcStride) {
    int gw = (blockIdx.x * blockDim.x + threadIdx.x) >> 5;
    if (gw >= nNodes * Bn) return;
    int node = gw % nNodes;
    int b    = gw / nNodes;
    int lane = threadIdx.x & 31;

    int s = off[node], e = off[node + 1];
    float4 a = make_float4(0.f, 0.f, 0.f, 0.f);
    const float* base = SRC + (size_t)b * srcStride;
    for (int j = s; j < e; ++j) {
        int src = lst[j];
        float4 v = reinterpret_cast<const float4*>(base + (size_t)src * H)[lane];
        a.x += v.x; a.y += v.y; a.z += v.z; a.w += v.w;
    }
    float sc = 1.0f / fmaxf((float)(e - s), 1.0f);
    a.x *= sc; a.y *= sc; a.z *= sc; a.w *= sc;
    reinterpret_cast<float4*>(agg + ((size_t)b * nNodes + node) * H)[lane] = a;
}

// ---------------- GEMM core: 256 thr, 128x128 tile, 8x8/thread, f32x2 ----------
__device__ __forceinline__ void mm_accum(const float* __restrict__ Xs,
                                         const float* __restrict__ Ws,
                                         int tr, int tc, u64 acc[8][4]) {
    const float* xbase = Xs + tr * 8 * 128;
    const float* wbase = Ws + 2 * tc;
#pragma unroll 4
    for (int k = 0; k < 128; k++) {
        u64 wv[4];
#pragma unroll
        for (int j = 0; j < 4; j++)
            wv[j] = *reinterpret_cast<const u64*>(wbase + k * 128 + 32 * j);
#pragma unroll
        for (int i = 0; i < 8; i++) {
            float xv = xbase[i * 128 + k];
            u64 xd;
            asm("mov.b64 %0, {%1, %1};" : "=l"(xd) : "f"(xv));
#pragma unroll
            for (int j = 0; j < 4; j++)
                asm("fma.rn.f32x2 %0, %1, %2, %0;"
                    : "+l"(acc[i][j]) : "l"(wv[j]), "l"(xd));
        }
    }
}

__device__ __forceinline__ void tile_load(const float* __restrict__ g,
                                          float* __restrict__ s, int t) {
    const float4* g4 = reinterpret_cast<const float4*>(g);
    float4* s4 = reinterpret_cast<float4*>(s);
#pragma unroll
    for (int i = 0; i < 16; i++) s4[t + 256 * i] = g4[t + 256 * i];
}

// ---------------- GEMM MODE 0: Y = X @ Wt ----------------
__global__ void __launch_bounds__(256, 1)
k_gemm0(const float* __restrict__ X, const float* __restrict__ Wt,
        float* __restrict__ out) {
    extern __shared__ float smx[];
    float* Xs = smx;
    float* Ws = smx + 128 * 128;
    const int t = threadIdx.x;
    const size_t row0 = (size_t)blockIdx.x * 128;

    tile_load(X + row0 * H, Xs, t);
    tile_load(Wt, Ws, t);
    __syncthreads();

    const int tc = t & 15, tr = t >> 4;
    u64 acc[8][4];
#pragma unroll
    for (int i = 0; i < 8; i++)
#pragma unroll
        for (int j = 0; j < 4; j++) acc[i][j] = 0ull;

    mm_accum(Xs, Ws, tr, tc, acc);

#pragma unroll
    for (int i = 0; i < 8; i++) {
        float* orow = out + (row0 + tr * 8 + i) * H + 2 * tc;
#pragma unroll
        for (int j = 0; j < 4; j++)
            *reinterpret_cast<u64*>(orow + 32 * j) = acc[i][j];
    }
}

// ---------------- Phase-1 E-side: self-GEMM + fused gather epilogue + LN ------
// out[b,e,:] = LN(hE + relu(hE@Wt + sig(ew[e])/max(deg,1) * sum_src Y[b,src,:] + bias))
__global__ void __launch_bounds__(256, 1)
k_gemmE(const float* __restrict__ X, const float* __restrict__ Wt,
        const float* __restrict__ Y,
        const int* __restrict__ off, const int* __restrict__ lst,
        const float* __restrict__ ew,
        const float* __restrict__ bias, const float* __restrict__ gamma,
        const float* __restrict__ beta, float* __restrict__ out) {
    extern __shared__ float smx[];
    float* Xs = smx;
    float* Ws = smx + 128 * 128;
    const int t = threadIdx.x;
    const size_t row0 = (size_t)blockIdx.x * 128;
    const int b = (int)(row0 / NE);
    const int e0 = (int)(row0 % NE);

    tile_load(X + row0 * H, Xs, t);
    tile_load(Wt, Ws, t);
    __syncthreads();

    const int tc = t & 15, tr = t >> 4;
    u64 acc[8][4];
#pragma unroll
    for (int i = 0; i < 8; i++)
#pragma unroll
        for (int j = 0; j < 4; j++) acc[i][j] = 0ull;

    mm_accum(Xs, Ws, tr, tc, acc);

    float2 b2[4], g2[4], be2[4];
#pragma unroll
    for (int j = 0; j < 4; j++) {
        b2[j]  = *reinterpret_cast<const float2*>(bias  + 2 * tc + 32 * j);
        g2[j]  = *reinterpret_cast<const float2*>(gamma + 2 * tc + 32 * j);
        be2[j] = *reinterpret_cast<const float2*>(beta  + 2 * tc + 32 * j);
    }
    const float* Yb = Y + (size_t)b * ND * H + 2 * tc;

#pragma unroll
    for (int i = 0; i < 8; i++) {
        const int e = e0 + tr * 8 + i;
        const size_t r = row0 + tr * 8 + i;
        int s = off[e], en = off[e + 1];
        float sc = (1.0f / (1.0f + __expf(-ew[e]))) / fmaxf((float)(en - s), 1.0f);

        float2 ag[4];
#pragma unroll
        for (int j = 0; j < 4; j++) ag[j] = make_float2(0.f, 0.f);
        for (int p = s; p < en; ++p) {
            const float* yr = Yb + (size_t)lst[p] * H;
#pragma unroll
            for (int j = 0; j < 4; j++) {
                float2 v = *reinterpret_cast<const float2*>(yr + 32 * j);
                ag[j].x += v.x; ag[j].y += v.y;
            }
        }

        float tv[8];
        float ssum = 0.f, q = 0.f;
#pragma unroll
        for (int j = 0; j < 4; j++) {
            float plo, phi;
            asm("mov.b64 {%0, %1}, %2;" : "=f"(plo), "=f"(phi) : "l"(acc[i][j]));
            float2 x2 = *reinterpret_cast<const float2*>(Xs + (tr * 8 + i) * 128 + 2 * tc + 32 * j);
            float t0 = plo + ag[j].x * sc + b2[j].x; t0 = fmaxf(t0, 0.f); t0 += x2.x;
            float t1 = phi + ag[j].y * sc + b2[j].y; t1 = fmaxf(t1, 0.f); t1 += x2.y;
            tv[2 * j] = t0; tv[2 * j + 1] = t1;
            ssum += t0 + t1;
            q += t0 * t0 + t1 * t1;
        }
#pragma unroll
        for (int o = 8; o; o >>= 1) {
            ssum += __shfl_xor_sync(0xffffffffu, ssum, o, 16);
            q    += __shfl_xor_sync(0xffffffffu, q, o, 16);
        }
        float m = ssum * (1.0f / 128.0f);
        float rstd = rsqrtf(q * (1.0f / 128.0f) - m * m + 1e-5f);
        float* orow = out + r * H + 2 * tc;
#pragma unroll
        for (int j = 0; j < 4; j++) {
            float2 o2;
            o2.x = (tv[2 * j]     - m) * rstd * g2[j].x + be2[j].x;
            o2.y = (tv[2 * j + 1] - m) * rstd * g2[j].y + be2[j].y;
            *reinterpret_cast<float2*>(orow + 32 * j) = o2;
        }
    }
}

// ---------------- Phase-2 D-side dual GEMM + LN -------------------------------
// out = LN(hD + relu(hD@W1 + aggPre@W2 + bias)) * gamma + beta
__global__ void __launch_bounds__(256, 1)
k_gemmD(const float* __restrict__ X, const float* __restrict__ W1t,
        const float* __restrict__ A, const float* __restrict__ W2t,
        const float* __restrict__ bias, const float* __restrict__ gamma,
        const float* __restrict__ beta, float* __restrict__ out) {
    extern __shared__ float smx[];
    float* Xs = smx;                   // hD tile (kept for residual)
    float* As = smx + 128 * 128;       // aggPre tile
    float* Ws = smx + 2 * 128 * 128;   // W buffer (reused)
    const int t = threadIdx.x;
    const size_t row0 = (size_t)blockIdx.x * 128;

    tile_load(X + row0 * H, Xs, t);
    tile_load(W1t, Ws, t);
    __syncthreads();

    const int tc = t & 15, tr = t >> 4;
    u64 acc[8][4];
#pragma unroll
    for (int i = 0; i < 8; i++)
#pragma unroll
        for (int j = 0; j < 4; j++) acc[i][j] = 0ull;

    mm_accum(Xs, Ws, tr, tc, acc);
    __syncthreads();                   // everyone done reading W1

    tile_load(A + row0 * H, As, t);
    tile_load(W2t, Ws, t);
    __syncthreads();

    mm_accum(As, Ws, tr, tc, acc);

    float2 b2[4], g2[4], be2[4];
#pragma unroll
    for (int j = 0; j < 4; j++) {
        b2[j]  = *reinterpret_cast<const float2*>(bias  + 2 * tc + 32 * j);
        g2[j]  = *reinterpret_cast<const float2*>(gamma + 2 * tc + 32 * j);
        be2[j] = *reinterpret_cast<const float2*>(beta  + 2 * tc + 32 * j);
    }
#pragma unroll
    for (int i = 0; i < 8; i++) {
        const size_t r = row0 + tr * 8 + i;
        float tv[8];
        float ssum = 0.f, q = 0.f;
#pragma unroll
        for (int j = 0; j < 4; j++) {
            float plo, phi;
            asm("mov.b64 {%0, %1}, %2;" : "=f"(plo), "=f"(phi) : "l"(acc[i][j]));
            float2 x2 = *reinterpret_cast<const float2*>(Xs + (tr * 8 + i) * 128 + 2 * tc + 32 * j);
            float t0 = plo + b2[j].x; t0 = fmaxf(t0, 0.f); t0 += x2.x;
            float t1 = phi + b2[j].y; t1 = fmaxf(t1, 0.f); t1 += x2.y;
            tv[2 * j] = t0; tv[2 * j + 1] = t1;
            ssum += t0 + t1;
            q += t0 * t0 + t1 * t1;
        }
#pragma unroll
        for (int o = 8; o; o >>= 1) {
            ssum += __shfl_xor_sync(0xffffffffu, ssum, o, 16);
            q    += __shfl_xor_sync(0xffffffffu, q, o, 16);
        }
        float m = ssum * (1.0f / 128.0f);
        float rstd = rsqrtf(q * (1.0f / 128.0f) - m * m + 1e-5f);
        float* orow = out + r * H + 2 * tc;
#pragma unroll
        for (int j = 0; j < 4; j++) {
            float2 o2;
            o2.x = (tv[2 * j]     - m) * rstd * g2[j].x + be2[j].x;
            o2.y = (tv[2 * j + 1] - m) * rstd * g2[j].y + be2[j].y;
            *reinterpret_cast<float2*>(orow + 32 * j) = o2;
        }
    }
}

// ---------------- launch ----------------
extern "C" void kernel_launch(void* const* d_in, const int* in_sizes, int n_in,
                              void* d_out, int out_size) {
    const float* hD    = (const float*)d_in[0];
    const float* hE    = (const float*)d_in[1];
    const int*   e_d2e = (const int*)d_in[2];
    const int*   e_e2d = (const int*)d_in[3];
    const float* ew    = (const float*)d_in[4];
    const float* W_d2e    = (const float*)d_in[5];
    const float* W_e_self = (const float*)d_in[6];
    const float* b_e   = (const float*)d_in[7];
    const float* g_e   = (const float*)d_in[8];
    const float* be_e  = (const float*)d_in[9];
    const float* W_e2d    = (const float*)d_in[10];
    const float* W_d_self = (const float*)d_in[11];
    const float* b_d   = (const float*)d_in[12];
    const float* g_d   = (const float*)d_in[13];
    const float* be_d  = (const float*)d_in[14];

    float* out_hD = (float*)d_out;
    float* out_hE = (float*)d_out + (size_t)Bn * ND * H;

    float *pY, *pAggPre, *pWt;
    int *pCntE, *pOffE, *pCurE, *pLstE, *pCntD, *pOffD, *pCurD, *pLstD;
    cudaGetSymbolAddress((void**)&pY, g_Y);
    cudaGetSymbolAddress((void**)&pAggPre, g_aggPre);
    cudaGetSymbolAddress((void**)&pWt, g_Wt);
    cudaGetSymbolAddress((void**)&pCntE, g_cntE);
    cudaGetSymbolAddress((void**)&pOffE, g_offE);
    cudaGetSymbolAddress((void**)&pCurE, g_curE);
    cudaGetSymbolAddress((void**)&pLstE, g_lstE);
    cudaGetSymbolAddress((void**)&pCntD, g_cntD);
    cudaGetSymbolAddress((void**)&pOffD, g_offD);
    cudaGetSymbolAddress((void**)&pCurD, g_curD);
    cudaGetSymbolAddress((void**)&pLstD, g_lstD);

    float* Wt_d2e    = pWt + 0 * H * H;
    float* Wt_e_self = pWt + 1 * H * H;
    float* Wt_e2d    = pWt + 2 * H * H;
    float* Wt_d_self = pWt + 3 * H * H;

    const int smem2 = 2 * 128 * 128 * (int)sizeof(float);  // 128 KB
    const int smem3 = 3 * 128 * 128 * (int)sizeof(float);  // 192 KB
    cudaFuncSetAttribute(k_gemm0, cudaFuncAttributeMaxDynamicSharedMemorySize, smem2);
    cudaFuncSetAttribute(k_gemmE, cudaFuncAttributeMaxDynamicSharedMemorySize, smem2);
    cudaFuncSetAttribute(k_gemmD, cudaFuncAttributeMaxDynamicSharedMemorySize, smem3);

    // ---- weight transposes + CSR build ----
    k_wt<<<64, 256>>>(W_d2e, Wt_d2e);
    k_wt<<<64, 256>>>(W_e_self, Wt_e_self);
    k_wt<<<64, 256>>>(W_e2d, Wt_e2d);
    k_wt<<<64, 256>>>(W_d_self, Wt_d_self);

    cudaMemsetAsync(pCntE, 0, NE * sizeof(int));
    cudaMemsetAsync(pCntD, 0, ND * sizeof(int));
    k_count<<<(NEDGE + 255) / 256, 256>>>(e_d2e, e_e2d);
    k_scan<<<1, 1024>>>(pCntE, pOffE, pCurE, NE);
    k_scan<<<1, 1024>>>(pCntD, pOffD, pCurD, ND);
    k_fill<<<(NEDGE + 255) / 256, 256>>>(e_d2e, e_e2d);

    // ---- Phase 1: D -> E ----
    k_gemm0<<<(Bn * ND) / 128, 256, smem2>>>(hD, Wt_d2e, pY);
    k_gemmE<<<(Bn * NE) / 128, 256, smem2>>>(hE, Wt_e_self, pY, pOffE, pLstE, ew,
                                             b_e, g_e, be_e, out_hE);

    // ---- Phase 2: E -> D (commuted aggregation + dual GEMM) ----
    k_agg<<<(ND * Bn * 32) / 256, 256>>>(out_hE, pOffD, pLstD, pAggPre, ND, (long)NE * H);
    k_gemmD<<<(Bn * ND) / 128, 256, smem3>>>(hD, Wt_d_self, pAggPre, Wt_e2d,
                                             b_d, g_d, be_d, out_hD);
}